// round 15
// baseline (speedup 1.0000x reference)
#include <cuda_runtime.h>
#include <cuda_bf16.h>
#include <stdint.h>

#define NTOK   16384
#define DIM    2048
#define NE     64
#define KTOP   8
#define ALPHA_C 0.001f

#define TM     32                  // tokens per CTA
#define NT     256                 // 8 warps: 2 m-tiles x 2 n-tiles x 2 k-halves
#define KC     64                  // k per chunk
#define NBLK   (NTOK / TM)         // 512 CTAs -> 3 per SM resident
#define NCH    (DIM / KC)          // 32 chunks
#define TAU    1e-4f               // near-tie fallback threshold (logit gap)

// smem: bf16 tiles, padded pitch 72 bf16 = 144B (ldmatrix rows -> banks 0,4,..,28)
#define APB    144
#define ATB    (32 * APB)          // 4608: one 32-row A tile (hi or lo)
#define BTB    (64 * APB)          // 9216: one 64-row B tile (hi or lo)
// A: 2 bufs x 2 terms at [0, 18432); B ring-2 x 2 terms at [18432, 55296)
#define ABASE(b, t) ((b) * 9216 + (t) * ATB)
#define BBASE(b, t) (18432 + (b) * 18432 + (t) * BTB)
#define DYN_BYTES 55296
// epilogue scratch carved from dead GEMM buffers (float offsets)
#define PR_OFF 3072
#define RC_OFF 3328
#define RP_OFF 3584

__device__ float g_cnt_part[NBLK][NE];
__device__ float g_prob_part[NBLK][NE];
__device__ unsigned int g_sync = 0;   // atomicInc wraps each launch -> graph-replay safe
__device__ __align__(16) __nv_bfloat16 g_Whi[NE * DIM];   // 256 KB
__device__ __align__(16) __nv_bfloat16 g_Wlo[NE * DIM];   // 256 KB

static __device__ __forceinline__ uint32_t smem_u32(const void* p) {
    uint32_t a;
    asm("{ .reg .u64 t; cvta.to.shared.u64 t, %1; cvt.u32.u64 %0, t; }" : "=r"(a) : "l"(p));
    return a;
}

// baseline-PTX tensor / async ops (sm_75/80+, valid for plain sm_103 target)
#define LDSM4(r, a) \
    asm volatile("ldmatrix.sync.aligned.m8n8.x4.shared.b16 {%0,%1,%2,%3}, [%4];" \
        : "=r"((r)[0]), "=r"((r)[1]), "=r"((r)[2]), "=r"((r)[3]) : "r"(a))

#define MMA(d, a, b) \
    asm volatile("mma.sync.aligned.m16n8k16.row.col.f32.bf16.bf16.f32 " \
        "{%0,%1,%2,%3}, {%4,%5,%6,%7}, {%8,%9}, {%0,%1,%2,%3};" \
        : "+f"((d)[0]), "+f"((d)[1]), "+f"((d)[2]), "+f"((d)[3]) \
        : "r"((a)[0]), "r"((a)[1]), "r"((a)[2]), "r"((a)[3]), "r"((b)[0]), "r"((b)[1]))

template <int N> static __device__ __forceinline__ void cp_wait() {
    asm volatile("cp.async.wait_group %0;" :: "n"(N) : "memory");
}

// fp32x4 -> bf16 hi (4) + bf16 lo (4), pairwise cvt (k order preserved)
static __device__ __forceinline__ void split4(float4 v, uint2& hi, uint2& lo) {
    __nv_bfloat162 h0 = __float22bfloat162_rn(make_float2(v.x, v.y));
    __nv_bfloat162 h1 = __float22bfloat162_rn(make_float2(v.z, v.w));
    float2 f0 = __bfloat1622float2(h0);
    float2 f1 = __bfloat1622float2(h1);
    __nv_bfloat162 l0 = __float22bfloat162_rn(make_float2(v.x - f0.x, v.y - f0.y));
    __nv_bfloat162 l1 = __float22bfloat162_rn(make_float2(v.z - f1.x, v.w - f1.y));
    hi.x = *reinterpret_cast<uint32_t*>(&h0);
    hi.y = *reinterpret_cast<uint32_t*>(&h1);
    lo.x = *reinterpret_cast<uint32_t*>(&l0);
    lo.y = *reinterpret_cast<uint32_t*>(&l1);
}

// -------- pre-pass: W fp32 -> bf16 hi/lo (identical split math -> bit-identical tiles) -----
__global__ void wconv_kernel(const float* __restrict__ W)
{
    int i = blockIdx.x * blockDim.x + threadIdx.x;   // over NE*DIM/4 = 32768
    float4 v = ((const float4*)W)[i];
    uint2 hi, lo; split4(v, hi, lo);
    ((uint2*)g_Whi)[i] = hi;
    ((uint2*)g_Wlo)[i] = lo;
}

// ---- gate-kernel chunk stages (TM=32: A = 32 rows x 16 float4 -> 2 LDG/thread) ----
static __device__ __forceinline__ void ldg_h(const float* Hb, int c, int tid, float4 (&ha)[2]) {
    const float* hp = Hb + c * KC;
#pragma unroll
    for (int g = 0; g < 2; g++) {
        int flat = tid + 256 * g, row = flat >> 4, f4 = flat & 15;
        ha[g] = *(const float4*)(hp + (size_t)row * DIM + f4 * 4);
    }
}
static __device__ __forceinline__ void sts_h(char* base, int buf, int tid, const float4 (&ha)[2]) {
#pragma unroll
    for (int g = 0; g < 2; g++) {
        int flat = tid + 256 * g, row = flat >> 4, f4 = flat & 15;
        int off = row * APB + f4 * 8;
        uint2 hi, lo;
        split4(ha[g], hi, lo);
        *(uint2*)(base + ABASE(buf, 0) + off) = hi;
        *(uint2*)(base + ABASE(buf, 1) + off) = lo;
    }
}
// B tile copy: preconverted bf16 from gmem, 4x cp.async 16B per thread, one commit group.
static __device__ __forceinline__ void b_cpasync(uint32_t dynb32, int c, int bufB, int tid) {
#pragma unroll
    for (int g = 0; g < 4; g++) {
        int flat = tid + 256 * g;
        int arr = flat >> 9, rem = flat & 511, row = rem >> 3, seg = rem & 7;
        const char* src = (const char*)(arr ? g_Wlo : g_Whi) +
                          ((size_t)row * DIM + c * KC) * 2 + seg * 16;
        uint32_t dst = dynb32 + BBASE(bufB, arr) + (uint32_t)(row * APB + seg * 16);
        asm volatile("cp.async.cg.shared.global [%0], [%1], 16;" :: "r"(dst), "l"(src) : "memory");
    }
    asm volatile("cp.async.commit_group;" ::: "memory");
}

// warp tile: m16 (rows (wid&1)*16) x n32 (cols ((wid>>1)&1)*32), k-half (wid>>2).
// Per k16-step: 6 LDSM4 : 12 HMMA, acc = 16 regs. Per-acc term order hh, hl, lh.
static __device__ __forceinline__ void compute_chunk(uint32_t dynb32, int bA, int bB,
                                                     int wid, int lane, float (&acc)[4][4]) {
    const uint32_t aHi = dynb32 + ABASE(bA, 0), aLo = dynb32 + ABASE(bA, 1);
    const uint32_t bHi = dynb32 + BBASE(bB, 0), bLo = dynb32 + BBASE(bB, 1);
    const int mrow = (wid & 1) * 16;
    const int ncol = ((wid >> 1) & 1) * 32;
    const int kh   = wid >> 2;
    const uint32_t aR = (uint32_t)((mrow + (lane & 15)) * APB + (lane >> 4) * 16);
    const uint32_t bR = (uint32_t)((ncol + (lane & 7) + ((lane >> 4) & 1) * 8) * APB +
                                   ((lane >> 3) & 1) * 16);
#pragma unroll
    for (int ss = 0; ss < 2; ss++) {
        const uint32_t so = (uint32_t)((kh * 2 + ss) * 32);
        uint32_t ah[4], al[4], bh[2][4], bl[2][4];
        LDSM4(ah, aHi + aR + so);
        LDSM4(al, aLo + aR + so);
        LDSM4(bh[0], bHi + bR + so);
        LDSM4(bh[1], bHi + bR + (uint32_t)(16 * APB) + so);
        LDSM4(bl[0], bLo + bR + so);
        LDSM4(bl[1], bLo + bR + (uint32_t)(16 * APB) + so);
        // term-major; same-acc revisit distance 4
#pragma unroll
        for (int j = 0; j < 4; j++) MMA(acc[j], ah, bh[j >> 1] + (j & 1) * 2);   // hh
#pragma unroll
        for (int j = 0; j < 4; j++) MMA(acc[j], ah, bl[j >> 1] + (j & 1) * 2);   // hl
#pragma unroll
        for (int j = 0; j < 4; j++) MMA(acc[j], al, bh[j >> 1] + (j & 1) * 2);   // lh
    }
}

__global__ __launch_bounds__(NT, 3)
void gate_kernel(const float* __restrict__ H, const float* __restrict__ W,
                 float* __restrict__ out, int out_size)
{
    extern __shared__ char dynsm[];
    __shared__ float rinv[TM];
    __shared__ float sm_cnt[NE];
    __shared__ unsigned int is_last;
    __shared__ int fb_cnt;
    __shared__ int fb_list[TM];

    const int tid  = threadIdx.x;
    const int blk  = blockIdx.x;
    const int wid  = tid >> 5;
    const int lane = tid & 31;
    char* base = dynsm;
    const uint32_t dynb32 = smem_u32(base);

    if (tid == 0) fb_cnt = 0;
    if (tid < NE) sm_cnt[tid] = 0.f;

    float acc[4][4];
#pragma unroll
    for (int j = 0; j < 4; j++)
#pragma unroll
        for (int q = 0; q < 4; q++) acc[j][q] = 0.f;

    const float* Hb = H + (size_t)blk * TM * DIM;

    // -------- GEMM: 3-term split-bf16 via HMMA; B ring-2 cp.async (issue-after-barrier) ----
    float4 ha[2];
    b_cpasync(dynb32, 0, 0, tid);          // group: chunk0 -> B ring 0
    ldg_h(Hb, 0, tid, ha);
    sts_h(base, 0, tid, ha);
    for (int c = 0; c < NCH; c++) {
        const int bA = c & 1;
        const bool more = (c + 1 < NCH);
        if (more) ldg_h(Hb, c + 1, tid, ha);
        cp_wait<0>();                      // B chunk c landed
        __syncthreads();                   // A sts(c) + B(c) visible; compute(c-1) done by all
        // B ring slot (c+1)&1 == (c-1)&1: last read at compute(c-1), done by all threads
        // (everyone passed this barrier) -> safe to overwrite; wait at next iter top covers it.
        if (more) b_cpasync(dynb32, c + 1, (c + 1) & 1, tid);
        compute_chunk(dynb32, bA, c & 1, wid, lane, acc);
        if (more) sts_h(base, bA ^ 1, tid, ha);
    }
    __syncthreads();   // all compute done; GEMM buffers dead -> reuse as epilogue scratch

    float (*logits)[NE + 1] = (float(*)[NE + 1])base;
    float* prS = (float*)base + PR_OFF;    // [4][NE]
    float* rcS = (float*)base + RC_OFF;    // [4][NE]
    float* rpS = (float*)base + RP_OFF;    // [4][NE]

    // -------- k-half partials -> logits smem (kh0 writes, kh1 adds) --------
    {
        const int mrow = (wid & 1) * 16;
        const int ncol = ((wid >> 1) & 1) * 32;
        const int kh   = wid >> 2;
        const int r  = lane >> 2;
        const int cb = (lane & 3) * 2;
        if (kh == 0) {
#pragma unroll
            for (int j = 0; j < 4; j++) {
                logits[mrow + r][ncol + cb + j * 8]         = acc[j][0];
                logits[mrow + r][ncol + cb + j * 8 + 1]     = acc[j][1];
                logits[mrow + r + 8][ncol + cb + j * 8]     = acc[j][2];
                logits[mrow + r + 8][ncol + cb + j * 8 + 1] = acc[j][3];
            }
        }
        __syncthreads();
        if (kh == 1) {
#pragma unroll
            for (int j = 0; j < 4; j++) {
                logits[mrow + r][ncol + cb + j * 8]         += acc[j][0];
                logits[mrow + r][ncol + cb + j * 8 + 1]     += acc[j][1];
                logits[mrow + r + 8][ncol + cb + j * 8]     += acc[j][2];
                logits[mrow + r + 8][ncol + cb + j * 8 + 1] += acc[j][3];
            }
        }
    }
    __syncthreads();

    // -------- near-tie detection: any adjacent gap in top-9 below TAU --------
    if (tid < TM) {
        float v[9];
#pragma unroll
        for (int j = 0; j < 9; j++) v[j] = -1e30f;
        for (int e = 0; e < NE; e++) {
            float nv = logits[tid][e];
#pragma unroll
            for (int j = 0; j < 9; j++) {
                if (nv > v[j]) { float t = v[j]; v[j] = nv; nv = t; }
            }
        }
        float mingap = 1e30f;
#pragma unroll
        for (int j = 0; j < 8; j++) mingap = fminf(mingap, v[j] - v[j + 1]);
        if (mingap < TAU) {
            int ix = atomicAdd(&fb_cnt, 1);
            fb_list[ix] = tid;
        }
    }
    __syncthreads();

    // -------- exact fp32 sequential-k fallback (R0 bit-exact), 4 tokens/pass --------
    {
        const int nfb = fb_cnt;
        for (int f0 = 0; f0 < nfb; f0 += 4) {
            const int fi = f0 + (tid >> 6);
            if (fi < nfb) {
                const int t = fb_list[fi];
                const int e = tid & 63;
                const float* hr = H + (size_t)(blk * TM + t) * DIM;
                const float* wr = W + (size_t)e * DIM;
                float a = 0.f;
                for (int k = 0; k < DIM; k += 4) {
                    float4 hv = *(const float4*)(hr + k);
                    float4 wv = *(const float4*)(wr + k);
                    a = fmaf(hv.x, wv.x, a);
                    a = fmaf(hv.y, wv.y, a);
                    a = fmaf(hv.z, wv.z, a);
                    a = fmaf(hv.w, wv.w, a);
                }
                logits[t][e] = a;
            }
        }
    }
    __syncthreads();

    // -------- per-token softmax + top-8 (proven R0 pipeline) --------
    if (tid < TM) {
        float m = -1e30f;
        for (int e = 0; e < NE; e++) m = fmaxf(m, logits[tid][e]);

        float s = 0.f;
        float val[KTOP]; int idx[KTOP];
#pragma unroll
        for (int j = 0; j < KTOP; j++) { val[j] = -1.f; idx[j] = 0; }
        for (int e = 0; e < NE; e++) {
            float ex = __expf(logits[tid][e] - m);
            logits[tid][e] = ex;   // stash exp for mean-prob pass
            s += ex;
            float nv = ex; int ni = e;
#pragma unroll
            for (int j = 0; j < KTOP; j++) {
                if (nv > val[j]) {
                    float tv = val[j]; val[j] = nv; nv = tv;
                    int   ti = idx[j]; idx[j] = ni; ni = ti;
                }
            }
        }
        rinv[tid] = 1.f / s;

        float ts = 0.f;
#pragma unroll
        for (int j = 0; j < KTOP; j++) ts += val[j];
        const float tinv = 1.f / ts;

        const int gt = blk * TM + tid;
        float* ow = out + (size_t)gt * KTOP;
        float* oi = out + (size_t)NTOK * KTOP + (size_t)gt * KTOP;
#pragma unroll
        for (int j = 0; j < KTOP; j++) {
            ow[j] = val[j] * tinv;
            oi[j] = (float)idx[j];
            atomicAdd(&sm_cnt[idx[j]], 1.f);  // integer counts: order-exact
        }
    }
    __syncthreads();

    // -------- per-block mean-prob partial (4 parts x 8 tokens) --------
    {
        const int e = tid & 63;
        const int p = tid >> 6;
        float sacc = 0.f;
        for (int t = p * 8; t < p * 8 + 8; t++)
            sacc += logits[t][e] * rinv[t];
        prS[p * NE + e] = sacc;
    }
    __syncthreads();
    if (tid < NE) {
        g_prob_part[blk][tid] = prS[tid] + prS[NE + tid] + prS[2 * NE + tid] + prS[3 * NE + tid];
        g_cnt_part[blk][tid]  = sm_cnt[tid];
    }

    // -------- last block finalizes the aux loss --------
    __threadfence();
    if (tid == 0)
        is_last = (atomicInc(&g_sync, NBLK - 1) == NBLK - 1);
    __syncthreads();
    if (is_last) {
        const int e = tid & 63;
        const int p = tid >> 6;       // 4 parts x 128 blocks, fixed order
        float c = 0.f, pm = 0.f;
        for (int b = p * 128; b < p * 128 + 128; b++) {
            c  += g_cnt_part[b][e];
            pm += g_prob_part[b][e];
        }
        rcS[p * NE + e] = c; rpS[p * NE + e] = pm;
        __syncthreads();
        if (tid == 0) {
            float s = 0.f;
            for (int e2 = 0; e2 < NE; e2++) {
                float C = rcS[e2] + rcS[NE + e2] + rcS[2 * NE + e2] + rcS[3 * NE + e2];
                float P = rpS[e2] + rpS[NE + e2] + rpS[2 * NE + e2] + rpS[3 * NE + e2];
                s += (C / (float)(NTOK * KTOP)) * (P / (float)NTOK);
            }
            const int pos = NTOK * KTOP * 2;
            if (pos < out_size) out[pos] = ALPHA_C * (float)NE * s;
        }
    }
}

extern "C" void kernel_launch(void* const* d_in, const int* in_sizes, int n_in,
                              void* d_out, int out_size)
{
    const float* H = (const float*)d_in[0];   // hidden_states (16384, 2048) fp32
    const float* W = (const float*)d_in[1];   // weight (64, 2048) fp32
    float* out = (float*)d_out;

    wconv_kernel<<<NE * DIM / 4 / 256, 256>>>(W);
    cudaFuncSetAttribute(gate_kernel, cudaFuncAttributeMaxDynamicSharedMemorySize, DYN_BYTES);
    gate_kernel<<<NBLK, NT, DYN_BYTES>>>(H, W, out, out_size);
}